// round 14
// baseline (speedup 1.0000x reference)
#include <cuda_runtime.h>
#include <cstddef>
#include <math.h>

#define T_ 4
#define B_ 16
#define C_ 256
#define N_ 512
#define H_ 1024
#define BK 16

// ---------------- scratch (device globals; no allocation allowed) ----------
__device__ __align__(16) float g_qs[(size_t)T_*B_*C_*N_];
__device__ __align__(16) float g_ks[(size_t)T_*B_*C_*N_];
__device__ __align__(16) float g_vs[(size_t)T_*B_*C_*N_];
__device__ __align__(16) float g_rs[(size_t)T_*B_*C_*N_];
__device__ __align__(16) float g_x1[(size_t)T_*B_*C_*N_];
__device__ __align__(16) float g_h [(size_t)T_*B_*H_*N_];

// transposed weights: WT[c*O + o] = W[o*Cin + c]  (values bit-identical)
__device__ __align__(16) float g_wtq[(size_t)C_*C_];
__device__ __align__(16) float g_wtk[(size_t)C_*C_];
__device__ __align__(16) float g_wtv[(size_t)C_*C_];
__device__ __align__(16) float g_wtp[(size_t)C_*C_];
__device__ __align__(16) float g_wt1[(size_t)H_*C_];
__device__ __align__(16) float g_wt2[(size_t)C_*H_];

__device__ __forceinline__ float* buf_ptr(int id){
  switch(id){
    case 0: return g_qs; case 1: return g_ks; case 2: return g_vs;
    case 3: return g_rs; case 4: return g_x1; default: return g_h;
  }
}
__device__ __forceinline__ float* wt_ptr(int id){
  switch(id){
    case 0: return g_wtq; case 1: return g_wtk; case 2: return g_wtv;
    case 3: return g_wtp; case 4: return g_wt1; default: return g_wt2;
  }
}

// ---------------- packed f32x2 helpers (bit-exact per-lane IEEE fma) -------
__device__ __forceinline__ unsigned long long pk2(float v){
  unsigned long long r; unsigned u = __float_as_uint(v);
  asm("mov.b64 %0, {%1, %1};" : "=l"(r) : "r"(u));
  return r;
}
__device__ __forceinline__ void fma2(unsigned long long &d,
                                     unsigned long long a, unsigned long long b){
  asm("fma.rn.f32x2 %0, %1, %2, %0;" : "+l"(d) : "l"(a), "l"(b));
}
__device__ __forceinline__ float2 unpk(unsigned long long p){
  unsigned lo, hi;
  asm("mov.b64 {%0, %1}, %2;" : "=r"(lo), "=r"(hi) : "l"(p));
  return make_float2(__uint_as_float(lo), __uint_as_float(hi));
}

// ---------------- cp.async helpers ----------------------------------------
__device__ __forceinline__ void cpa16(void* smem_dst, const void* gmem_src){
  unsigned d = (unsigned)__cvta_generic_to_shared(smem_dst);
  asm volatile("cp.async.cg.shared.global [%0], [%1], 16;" :: "r"(d), "l"(gmem_src));
}
#define CPA_COMMIT()   asm volatile("cp.async.commit_group;")
#define CPA_WAIT_ALL() asm volatile("cp.async.wait_group 0;" ::: "memory")

// ------------- prep: transpose weights -------------------------------------
// FIX vs R12: destination resolved DEVICE-SIDE via wt_ptr(wid). Passing a
// __device__ global as a host-side kernel arg passes the host shadow address
// (ATS made the stray writes silently land in host memory -> WT stayed zero).
__global__ void prep_wt(const float* __restrict__ W, int wid, int O, int Cin){
  float* WT = wt_ptr(wid);
  int i = blockIdx.x * blockDim.x + threadIdx.x;
  int tot = O * Cin;
  for (; i < tot; i += gridDim.x * blockDim.x){
    int c = i / O, o = i % O;                 // contiguous writes along o
    WT[i] = W[(size_t)o * Cin + c];
  }
}

// ------------- fused GEMM + (reference-order) BN + LIF scan over T
// Arithmetic byte-identical to R11: serial ascending-c fp32 fma per output;
// FFMA2 pairs ADJACENT O-ROWS (b-operand = duplicated X pair) -> bit-exact.
// Block tile: 128(o) x 32(n) x 4(t), 128 threads, micro 16(o) x 2(n) x 4(t).
// BK=16, 2 stages: W via cp.async from WT (layout-native), X via register
// prefetch + dup STS. One barrier + one wait_group per 16 k.
#define XROW 320   // 16 n-pairs * 20 floats (n-even 8, n-odd 8, pad 4)
struct SmemLayout {
  float sW [2][BK][128];    // [stage][k][o]
  float sX2[2][BK][XROW];   // dup pairs [stage][k][col]
  float sBN[4][128];        // s, mean, beta, convbias
};

__device__ __forceinline__ void gemm_lif_body(
    const float* __restrict__ X, float* __restrict__ out,
    const float* __restrict__ res,
    const float* __restrict__ WT, const float* __restrict__ bn,
    const float* __restrict__ bias, int Cin, int Cout,
    int b, int o0, int n0)
{
  extern __shared__ __align__(16) unsigned char smem_raw[];
  SmemLayout* sm = reinterpret_cast<SmemLayout*>(smem_raw);

  const int tid = threadIdx.x;
  const int to = tid >> 4;          // 0..7  -> o micro group (16 o each)
  const int tn = tid & 15;          // 0..15 -> n pair (2 each)

  // W cp.async map: 4 chunks/thread: k = i*4 + (tid>>5), o-group co = tid&31
  const int wk = tid >> 5;          // 0..3
  const int wc = tid & 31;          // 0..31 (4 o's per chunk)
  // X staging: xk = k row (0..15), xt = t, xh = n-half (16 n)
  const int xk = tid >> 3;          // 0..15
  const int xt = (tid >> 1) & 3;    // 0..3
  const int xh = tid & 1;           // 0..1

  {
    const int o = o0 + tid;
    sm->sBN[0][tid] = bn[o] / sqrtf(bn[3*Cout + o] + 1e-5f);
    sm->sBN[1][tid] = bn[2*Cout + o];
    sm->sBN[2][tid] = bn[Cout + o];
    sm->sBN[3][tid] = bias ? bias[o] : 0.0f;
  }

  // W async prefetch: one BK-tile into stage s
  auto cpa_w = [&](int s, int kk){
#pragma unroll
    for (int i=0;i<4;i++){
      const int k = i*4 + wk;
      cpa16(&sm->sW[s][k][wc*4], WT + (size_t)(kk + k) * Cout + o0 + wc*4);
    }
  };

  // X register prefetch (16 floats = 4 float4)
  float4 rx[4];
  auto ldg_x = [&](int kk){
    const float* xp = X + ((size_t)(xt*B_ + b) * Cin + kk + xk) * N_ + n0 + xh*16;
#pragma unroll
    for (int i=0;i<4;i++) rx[i] = *(const float4*)(xp + i*4);
  };
  auto sts_x = [&](int s){
#pragma unroll
    for (int i=0;i<4;i++){
      float xv[4] = {rx[i].x, rx[i].y, rx[i].z, rx[i].w};
#pragma unroll
      for (int j=0;j<4;j++){
        const int nl = xh*16 + i*4 + j;                 // local n 0..31
        const int col = (nl>>1)*20 + (nl&1)*8 + xt*2;   // dup pair slot
        *(unsigned long long*)&sm->sX2[s][xk][col] = pk2(xv[j]);
      }
    }
  };

  // accp[p][j]: packed (o = to*16+2p, +1), j = n*4 + t  (n in 0..1, t in 0..3)
  unsigned long long accp[8][8];
#pragma unroll
  for (int i=0;i<8;i++)
#pragma unroll
    for (int j=0;j<8;j++) accp[i][j] = 0ULL;

  auto compute = [&](int s){
#pragma unroll
    for (int k = 0; k < BK; k++){
      const float* wp = &sm->sW[s][k][to*16];
      ulonglong2 w01 = *(const ulonglong2*)(wp);
      ulonglong2 w23 = *(const ulonglong2*)(wp + 4);
      ulonglong2 w45 = *(const ulonglong2*)(wp + 8);
      ulonglong2 w67 = *(const ulonglong2*)(wp + 12);
      unsigned long long ap[8] = {w01.x,w01.y,w23.x,w23.y,
                                  w45.x,w45.y,w67.x,w67.y};
      const float* bp = &sm->sX2[s][k][tn*20];
      ulonglong2 q0 = *(const ulonglong2*)(bp);      // (n0,t0),(n0,t1)
      ulonglong2 q1 = *(const ulonglong2*)(bp + 4);  // (n0,t2),(n0,t3)
      ulonglong2 q2 = *(const ulonglong2*)(bp + 8);  // (n1,t0),(n1,t1)
      ulonglong2 q3 = *(const ulonglong2*)(bp + 12); // (n1,t2),(n1,t3)
      unsigned long long pb[8] = {q0.x,q0.y,q1.x,q1.y,q2.x,q2.y,q3.x,q3.y};
#pragma unroll
      for (int j=0; j<8; j++){    // j outer: pb[j] reused by 8 consecutive FFMA2
#pragma unroll
        for (int p=0; p<8; p++) fma2(accp[p][j], ap[p], pb[j]);
      }
    }
  };

  const int ntile = Cin / BK;     // 16 or 64: always even
  cpa_w(0, 0); CPA_COMMIT();
  ldg_x(0);

#pragma unroll 1
  for (int it = 0; it < ntile; it += 2){
    // ---- stage 0: tile it ----
    sts_x(0);
    CPA_WAIT_ALL();               // W(stage0) group complete
    __syncthreads();
    cpa_w(1, (it + 1) * BK); CPA_COMMIT();   // safe: all passed barrier ->
    ldg_x((it + 1) * BK);                    // readers of stage1 (it-1) done
    compute(0);
    // ---- stage 1: tile it+1 ----
    sts_x(1);
    CPA_WAIT_ALL();               // W(stage1) group complete
    __syncthreads();
    if (it + 2 < ntile){
      cpa_w(0, (it + 2) * BK); CPA_COMMIT();
      ldg_x((it + 2) * BK);
    }
    compute(1);
  }

  // epilogue: bias -> BN (reference order) -> LIF scan over t -> +residual
#pragma unroll
  for (int p=0; p<8; p++) {
    float accs[2][8];    // [o-lane within pair][j = n*4 + t]
#pragma unroll
    for (int j=0;j<8;j++){
      float2 pr = unpk(accp[p][j]);
      accs[0][j] = pr.x; accs[1][j] = pr.y;
    }
#pragma unroll
    for (int h2=0; h2<2; h2++) {
      const int oloc = to*16 + 2*p + h2;
      const int o = o0 + oloc;
      const float s_  = sm->sBN[0][oloc];
      const float m_  = sm->sBN[1][oloc];
      const float be_ = sm->sBN[2][oloc];
      const float bc_ = sm->sBN[3][oloc];
#pragma unroll
      for (int n=0; n<2; n++) {
        float mem = 0.0f;
        float sp[4];
#pragma unroll
        for (int t=0; t<4; t++) {
          float ypre = accs[h2][n*4 + t] + bc_;            // conv bias (0 if none)
          float y    = fmaf(ypre - m_, s_, be_);           // (y-m)*s + beta
          float m2   = mem + (y - mem) * 0.5f;             // mem + (y-mem)/TAU
          bool fire  = (m2 > 0.5f);                        // spike(mem - 0.5)
          mem = fire ? 0.0f : m2;                          // hard reset
          sp[t] = fire ? 1.0f : 0.0f;
        }
#pragma unroll
        for (int t=0; t<4; t++) {
          const size_t idx = ((size_t)(t*B_ + b) * Cout + o) * N_ + n0 + tn*2 + n;
          float v = sp[t];
          if (res) v += res[idx];
          out[idx] = v;
        }
      }
    }
  }
}

// q,k,v fused: blockIdx.y in [0,6): gemm = gy>>1, o0 = (gy&1)*128
__global__ __launch_bounds__(128, 2)
void qkv_gemm_kernel(const float* __restrict__ x,
                     const float* __restrict__ bnq,
                     const float* __restrict__ bnk,
                     const float* __restrict__ bnv)
{
  const int gy = blockIdx.y;
  const int gemm = gy >> 1;
  const int o0 = (gy & 1) * 128;
  const float* WT = wt_ptr(gemm);
  const float* bn = (gemm == 0) ? bnq : (gemm == 1) ? bnk : bnv;
  float* out = buf_ptr(gemm);
  gemm_lif_body(x, out, nullptr, WT, bn, nullptr, C_, C_,
                blockIdx.z, o0, blockIdx.x * 32);
}

__global__ __launch_bounds__(128, 2)
void gemm_lif_kernel(const float* __restrict__ Xext, float* __restrict__ outext,
                     const float* __restrict__ resext,
                     int xid, int oid, int rid, int wid,
                     const float* __restrict__ bn,
                     const float* __restrict__ bias, int Cin, int Cout)
{
  const float* X   = (xid >= 0) ? buf_ptr(xid) : Xext;
  float* out       = (oid >= 0) ? buf_ptr(oid) : outext;
  const float* res = (rid == -2) ? nullptr : ((rid >= 0) ? buf_ptr(rid) : resext);
  const float* WT  = wt_ptr(wid);
  gemm_lif_body(X, out, res, WT, bn, bias, Cin, Cout,
                blockIdx.z, blockIdx.y * 128, blockIdx.x * 32);
}

// ------------- spiking linear attention + attn-LIF (bit-exact integer math)
// KV[d1][d2] = sum_m k[d1,m]*v[d2,m] via ballot-bitpack + popc (spikes binary)
// r = 0.0625 * q @ KV ; LIF over t (dyadic-exact).
__global__ __launch_bounds__(256)
void attn_lif_kernel()
{
  __shared__ unsigned kb[16][17], vb[16][17];
  __shared__ float sKV[16][17];
  const int b = blockIdx.x;
  const int h = blockIdx.y;
  const int tid = threadIdx.x;
  const int warp = tid >> 5, lane = tid & 31;
  const int d1 = tid >> 4, d2 = tid & 15;

  float mem[2][16];
#pragma unroll
  for (int j=0;j<2;j++)
#pragma unroll
    for (int d=0; d<16; d++) mem[j][d] = 0.0f;

#pragma unroll 1
  for (int t=0; t<T_; t++){
    const size_t base = ((size_t)(t*B_ + b) * C_ + h*16) * N_;
    __syncthreads();   // prior iteration done reading kb/vb/sKV

#pragma unroll 4
    for (int i = 0; i < 32; i++){
      const int idx = warp * 32 + i;          // 0..255
      const int row = idx >> 4, word = idx & 15;
      const size_t off = base + (size_t)row * N_ + word * 32 + lane;
      unsigned uk = __ballot_sync(0xffffffffu, g_ks[off] != 0.0f);
      unsigned uv = __ballot_sync(0xffffffffu, g_vs[off] != 0.0f);
      if (lane == 0){ kb[row][word] = uk; vb[row][word] = uv; }
    }
    __syncthreads();

    {
      int kv = 0;
#pragma unroll
      for (int w=0; w<16; w++) kv += __popc(kb[d1][w] & vb[d2][w]);
      sKV[d1][d2] = (float)kv;
    }
    __syncthreads();

#pragma unroll
    for (int half=0; half<2; half++){
      const int n = tid + half*256;
      float qv[16];
#pragma unroll
      for (int dd=0; dd<16; dd++) qv[dd] = g_qs[base + (size_t)dd*N_ + n];
#pragma unroll
      for (int d=0; d<16; d++){
        float r = 0.0f;
#pragma unroll
        for (int dd=0; dd<16; dd++) r = fmaf(qv[dd], sKV[dd][d], r);
        r *= 0.0625f;
        float m2 = mem[half][d] + (r - mem[half][d]) * 0.5f;
        bool fire = (m2 > 0.5f);
        mem[half][d] = fire ? 0.0f : m2;
        g_rs[base + (size_t)d*N_ + n] = fire ? 1.0f : 0.0f;
      }
    }
  }
}

// --------------------------------------------------------------------------
extern "C" void kernel_launch(void* const* d_in, const int* in_sizes, int n_in,
                              void* d_out, int out_size)
{
  const float* x       = (const float*)d_in[0];
  const float* q_w     = (const float*)d_in[1];
  const float* q_bn    = (const float*)d_in[2];
  const float* k_w     = (const float*)d_in[3];
  const float* k_bn    = (const float*)d_in[4];
  const float* v_w     = (const float*)d_in[5];
  const float* v_bn    = (const float*)d_in[6];
  const float* proj_w  = (const float*)d_in[7];
  const float* proj_bn = (const float*)d_in[8];
  const float* fc1_w   = (const float*)d_in[9];
  const float* fc1_b   = (const float*)d_in[10];
  const float* fc1_bn  = (const float*)d_in[11];
  const float* fc2_w   = (const float*)d_in[12];
  const float* fc2_b   = (const float*)d_in[13];
  const float* fc2_bn  = (const float*)d_in[14];
  float* out = (float*)d_out;

  const int smem_bytes = (int)sizeof(SmemLayout);   // ~58KB, needs opt-in
  cudaFuncSetAttribute(qkv_gemm_kernel,
      cudaFuncAttributeMaxDynamicSharedMemorySize, smem_bytes);
  cudaFuncSetAttribute(gemm_lif_kernel,
      cudaFuncAttributeMaxDynamicSharedMemorySize, smem_bytes);

  // prep: transpose weights into device-global WT buffers (device-side dst!)
  prep_wt<<<256, 256>>>(q_w,    0, C_, C_);
  prep_wt<<<256, 256>>>(k_w,    1, C_, C_);
  prep_wt<<<256, 256>>>(v_w,    2, C_, C_);
  prep_wt<<<256, 256>>>(proj_w, 3, C_, C_);
  prep_wt<<<512, 256>>>(fc1_w,  4, H_, C_);
  prep_wt<<<512, 256>>>(fc2_w,  5, C_, H_);

  dim3 blk(128);

  // q, k, v = conv+bn+lif(x) -> binary spikes (one fused launch, t in-register)
  qkv_gemm_kernel<<<dim3(N_/32, 6, B_), blk, smem_bytes>>>(x, q_bn, k_bn, v_bn);

  // linear attention (q (kT v)) * 0.0625 + attn-LIF -> g_rs
  attn_lif_kernel<<<dim3(B_, 16), dim3(256)>>>();

  // proj conv+bn+lif, fused residual: x1 = x + spike
  gemm_lif_kernel<<<dim3(N_/32, C_/128, B_), blk, smem_bytes>>>(
      nullptr, nullptr, x, 3, 4, -1, 3, proj_bn, nullptr, C_, C_);

  // fc1 conv+bn+lif -> g_h (Cout=1024)
  gemm_lif_kernel<<<dim3(N_/32, H_/128, B_), blk, smem_bytes>>>(
      nullptr, nullptr, nullptr, 4, 5, -2, 4, fc1_bn, fc1_b, C_, H_);

  // fc2 conv+bn+lif, fused residual: out = x1 + spike (Cin=1024)
  gemm_lif_kernel<<<dim3(N_/32, C_/128, B_), blk, smem_bytes>>>(
      nullptr, out, nullptr, 5, -1, 4, 5, fc2_bn, fc2_b, H_, C_);
}